// round 1
// baseline (speedup 1.0000x reference)
#include <cuda_runtime.h>
#include <math.h>

// SupCon loss, N=8192, D=512, T=0.1
// loss = sum_i( lse_{j!=i}(s_ij) - mean_{pos j}(s_ij) ) * T / N,  s_ij = <e_i,e_j>/T

#define NPTS 8192
#define DDIM 512
#define BM 64
#define BN 256
#define BK 8
#define TM 8
#define TN 8
#define NTHREADS 256
#define NTILES (NPTS / BN)   // 32

__device__ __forceinline__ float ex2f(float x) {
    float y;
    asm("ex2.approx.f32 %0, %1;" : "=f"(y) : "f"(x));
    return y;
}

__global__ void supcon_zero(float* out) { *out = 0.0f; }

__global__ void __launch_bounds__(NTHREADS, 1)
supcon_kernel(const float* __restrict__ emb,
              const long long* __restrict__ labels,
              float* __restrict__ out)
{
    extern __shared__ float smem[];
    float* As = smem;                       // [DDIM][BM]  (k-major, row minor) 128KB
    float* Bs = smem + DDIM * BM;           // [BK][BN]    8KB
    int*   cl = (int*)(Bs + BK * BN);       // [BN] column labels

    const int t    = threadIdx.x;
    const int lane = t & 31;                // column group
    const int wid  = t >> 5;                // row group (0..7), one warp per row group
    const int row0 = blockIdx.x * BM;

    // ---- Load A panel transposed into SMEM: As[k*BM + r] = emb[row0+r][k] ----
    // consecutive threads -> consecutive r (conflict-free STS)
    for (int idx = t; idx < BM * (DDIM / 4); idx += NTHREADS) {
        int r  = idx & (BM - 1);
        int kq = idx >> 6;                  // idx / BM
        float4 v = reinterpret_cast<const float4*>(emb + (size_t)(row0 + r) * DDIM)[kq];
        int kb = kq * 4;
        As[(kb + 0) * BM + r] = v.x;
        As[(kb + 1) * BM + r] = v.y;
        As[(kb + 2) * BM + r] = v.z;
        As[(kb + 3) * BM + r] = v.w;
    }

    // per-thread online state for TM rows
    float m[TM], l[TM], ps[TM];
    int   cnt[TM], rlab[TM];
#pragma unroll
    for (int r = 0; r < TM; r++) {
        m[r] = -1e30f; l[r] = 0.0f; ps[r] = 0.0f; cnt[r] = 0;
        rlab[r] = (int)labels[row0 + wid * TM + r];
    }

    const float C = 14.4269504088896341f;   // 1/(T*ln2), T = 0.1

    __syncthreads();                        // As visible

    for (int tile = 0; tile < NTILES; ++tile) {
        const int col0 = tile * BN;
        cl[t] = (int)labels[col0 + t];      // covered by first sync in k-loop

        float acc[TM][TN];
#pragma unroll
        for (int r = 0; r < TM; r++)
#pragma unroll
            for (int c = 0; c < TN; c++) acc[r][c] = 0.0f;

        const float* gB = emb + (size_t)(col0 + t) * DDIM;
        float4 pb0 = reinterpret_cast<const float4*>(gB)[0];
        float4 pb1 = reinterpret_cast<const float4*>(gB)[1];

        for (int kt = 0; kt < DDIM; kt += BK) {
            __syncthreads();                // previous chunk fully consumed
            Bs[0 * BN + t] = pb0.x; Bs[1 * BN + t] = pb0.y;
            Bs[2 * BN + t] = pb0.z; Bs[3 * BN + t] = pb0.w;
            Bs[4 * BN + t] = pb1.x; Bs[5 * BN + t] = pb1.y;
            Bs[6 * BN + t] = pb1.z; Bs[7 * BN + t] = pb1.w;
            if (kt + BK < DDIM) {
                pb0 = reinterpret_cast<const float4*>(gB + kt + BK)[0];
                pb1 = reinterpret_cast<const float4*>(gB + kt + BK + 4)[0];
            }
            __syncthreads();

#pragma unroll
            for (int kk = 0; kk < BK; ++kk) {
                const int k = kt + kk;
                // A: warp-broadcast (all lanes same address)
                float4 a0 = *reinterpret_cast<const float4*>(&As[k * BM + wid * TM]);
                float4 a1 = *reinterpret_cast<const float4*>(&As[k * BM + wid * TM + 4]);
                // B: two lane*4 groups -> conflict-free LDS.128 phases
                float4 b0 = *reinterpret_cast<const float4*>(&Bs[kk * BN + lane * 4]);
                float4 b1 = *reinterpret_cast<const float4*>(&Bs[kk * BN + 128 + lane * 4]);
                float a[TM] = {a0.x, a0.y, a0.z, a0.w, a1.x, a1.y, a1.z, a1.w};
                float b[TN] = {b0.x, b0.y, b0.z, b0.w, b1.x, b1.y, b1.z, b1.w};
#pragma unroll
                for (int r = 0; r < TM; r++)
#pragma unroll
                    for (int c = 0; c < TN; c++)
                        acc[r][c] = fmaf(a[r], b[c], acc[r][c]);
            }
        }

        // ---- fused epilogue: online lse + positive sums ----
        int gc[TN];
#pragma unroll
        for (int c = 0; c < TN; c++)
            gc[c] = col0 + ((c < 4) ? (lane * 4 + c) : (128 + lane * 4 + (c - 4)));

#pragma unroll
        for (int r = 0; r < TM; r++) {
            const int grow = row0 + wid * TM + r;
            float s2[TN];
            float tmax = -1e30f;
#pragma unroll
            for (int c = 0; c < TN; c++) {
                s2[c] = acc[r][c] * C;
                if (gc[c] == grow) s2[c] = -1e30f;   // exclude diagonal
                tmax = fmaxf(tmax, s2[c]);
            }
            float mn = fmaxf(m[r], tmax);
            float al = l[r] * ex2f(m[r] - mn);
#pragma unroll
            for (int c = 0; c < TN; c++) al += ex2f(s2[c] - mn);
            m[r] = mn; l[r] = al;

            const int rl = rlab[r];
#pragma unroll
            for (int c = 0; c < TN; c++) {
                if (cl[gc[c] - col0] == rl && gc[c] != grow) {
                    ps[r] += acc[r][c];
                    cnt[r] += 1;
                }
            }
        }
        __syncthreads();   // protect cl[] before next tile overwrites it
    }

    // ---- combine 32 column-lanes of each warp (rows are warp-private) ----
#pragma unroll
    for (int off = 16; off > 0; off >>= 1) {
#pragma unroll
        for (int r = 0; r < TM; r++) {
            float mo = __shfl_down_sync(0xFFFFFFFFu, m[r], off);
            float lo = __shfl_down_sync(0xFFFFFFFFu, l[r], off);
            float po = __shfl_down_sync(0xFFFFFFFFu, ps[r], off);
            int   co = __shfl_down_sync(0xFFFFFFFFu, cnt[r], off);
            float mn = fmaxf(m[r], mo);
            l[r] = l[r] * ex2f(m[r] - mn) + lo * ex2f(mo - mn);
            m[r] = mn;
            ps[r] += po;
            cnt[r] += co;
        }
    }

    if (lane == 0) {
        const float LN2 = 0.6931471805599453f;
        const float T   = 0.1f;
        float sum = 0.0f;
#pragma unroll
        for (int r = 0; r < TM; r++) {
            float lse2 = m[r] + log2f(l[r]);            // log2-domain lse
            // contribution: lse*T/N - possum_raw/(cnt*N)
            sum += lse2 * (LN2 * T / (float)NPTS) - ps[r] / ((float)cnt[r] * (float)NPTS);
        }
        atomicAdd(out, sum);
    }
}

extern "C" void kernel_launch(void* const* d_in, const int* in_sizes, int n_in,
                              void* d_out, int out_size)
{
    const float*     emb    = (const float*)d_in[0];
    const long long* labels = (const long long*)d_in[1];
    float*           out    = (float*)d_out;

    size_t smem = (size_t)(DDIM * BM + BK * BN) * sizeof(float) + BN * sizeof(int);
    cudaFuncSetAttribute(supcon_kernel, cudaFuncAttributeMaxDynamicSharedMemorySize, (int)smem);

    supcon_zero<<<1, 1>>>(out);
    supcon_kernel<<<NPTS / BM, NTHREADS, smem>>>(emb, labels, out);
}

// round 3
// speedup vs baseline: 5.7898x; 5.7898x over previous
#include <cuda_runtime.h>
#include <cuda_bf16.h>
#include <cstdint>
#include <math.h>

// SupCon loss, N=8192, D=512, T=0.1
// mma.sync bf16 tensor-core GEMM (compute_103-safe PTX) + fused online-softmax epilogue.

#define NPTS 8192
#define DDIM 512

__device__ __nv_bfloat16 g_ebf[NPTS * DDIM];       // 8 MB bf16 copy of embeddings
__device__ float4 g_part[256][NPTS];               // 32 MB per-(colslot,row) partials

__device__ __forceinline__ uint32_t smem_u32(const void* p) {
    uint32_t a;
    asm("{ .reg .u64 t; cvta.to.shared.u64 t, %1; cvt.u32.u64 %0, t; }" : "=r"(a) : "l"(p));
    return a;
}
__device__ __forceinline__ float ex2f(float x) {
    float y; asm("ex2.approx.f32 %0, %1;" : "=f"(y) : "f"(x)); return y;
}
__device__ __forceinline__ void cpasync16(uint32_t saddr, const void* g) {
    asm volatile("cp.async.cg.shared.global [%0], [%1], 16;" :: "r"(saddr), "l"(g));
}
__device__ __forceinline__ void ldsm4(uint32_t* r, uint32_t addr) {
    asm volatile("ldmatrix.sync.aligned.m8n8.x4.shared.b16 {%0,%1,%2,%3}, [%4];"
                 : "=r"(r[0]), "=r"(r[1]), "=r"(r[2]), "=r"(r[3]) : "r"(addr));
}
__device__ __forceinline__ void mma_bf16(float* c, const uint32_t* a, uint32_t b0, uint32_t b1) {
    asm volatile("mma.sync.aligned.m16n8k16.row.col.f32.bf16.bf16.f32 "
                 "{%0,%1,%2,%3}, {%4,%5,%6,%7}, {%8,%9}, {%0,%1,%2,%3};"
                 : "+f"(c[0]), "+f"(c[1]), "+f"(c[2]), "+f"(c[3])
                 : "r"(a[0]), "r"(a[1]), "r"(a[2]), "r"(a[3]), "r"(b0), "r"(b1));
}

// ---------------- fp32 -> bf16 conversion ----------------
__global__ void __launch_bounds__(256)
conv_kernel(const float* __restrict__ emb)
{
    int i = (blockIdx.x * 256 + threadIdx.x) * 8;
    float4 v0 = *reinterpret_cast<const float4*>(emb + i);
    float4 v1 = *reinterpret_cast<const float4*>(emb + i + 4);
    __nv_bfloat162 b0 = __float22bfloat162_rn(make_float2(v0.x, v0.y));
    __nv_bfloat162 b1 = __float22bfloat162_rn(make_float2(v0.z, v0.w));
    __nv_bfloat162 b2 = __float22bfloat162_rn(make_float2(v1.x, v1.y));
    __nv_bfloat162 b3 = __float22bfloat162_rn(make_float2(v1.z, v1.w));
    uint4 o;
    o.x = *reinterpret_cast<uint32_t*>(&b0);
    o.y = *reinterpret_cast<uint32_t*>(&b1);
    o.z = *reinterpret_cast<uint32_t*>(&b2);
    o.w = *reinterpret_cast<uint32_t*>(&b3);
    *reinterpret_cast<uint4*>(g_ebf + i) = o;
}

__global__ void supcon_zero(float* out) { *out = 0.0f; }

// ---------------- GEMM tile + fused epilogue ----------------
// CTA: 128x128 tile of S. 8 warps: warp grid 2(M) x 4(N), warp tile 64x32.
// K=512 in 16 stages of 32, double-buffered cp.async.
// SMEM tile row = 64B (32 bf16) = 4 x 16B chunks; chunk swizzle q^((row>>1)&3)
// makes every 8-row x 16B ldmatrix group bank-conflict-free.
__global__ void __launch_bounds__(256, 2)
supcon_gemm(const long long* __restrict__ labels)
{
    __shared__ __align__(128) __nv_bfloat16 As[2][128 * 32];
    __shared__ __align__(128) __nv_bfloat16 Bs[2][128 * 32];
    __shared__ int rlab_s[128], clab_s[128];

    const int tid = threadIdx.x;
    const int wid = tid >> 5, lane = tid & 31;
    const int warp_m = wid >> 2, warp_n = wid & 3;
    const int I = blockIdx.y, J = blockIdx.x;
    const int row0 = I * 128, col0 = J * 128;

    if (tid < 128) rlab_s[tid] = (int)labels[row0 + tid];
    else           clab_s[tid - 128] = (int)labels[col0 + tid - 128];

    const uint32_t aBase = smem_u32(As);
    const uint32_t bBase = smem_u32(Bs);

    // cp.async mapping: thread -> (row = tid>>1, chunks q0,q0+1), 32B contiguous gmem
    const int ldr = tid >> 1;
    const int ldq = (tid & 1) * 2;
    const int ldsw = (ldr >> 1) & 3;
    const uint32_t sA0 = aBase + ldr * 64 + ((ldq ^ ldsw) * 16);
    const uint32_t sA1 = aBase + ldr * 64 + (((ldq + 1) ^ ldsw) * 16);
    const uint32_t sB0 = bBase + ldr * 64 + ((ldq ^ ldsw) * 16);
    const uint32_t sB1 = bBase + ldr * 64 + (((ldq + 1) ^ ldsw) * 16);
    const __nv_bfloat16* gA = g_ebf + (size_t)(row0 + ldr) * DDIM + ldq * 8;
    const __nv_bfloat16* gB = g_ebf + (size_t)(col0 + ldr) * DDIM + ldq * 8;

    // ldmatrix lane geometry
    const int lrowA = warp_m * 64 + ((lane >> 3) & 1) * 8 + (lane & 7);   // + mf*16
    const int lrowB = warp_n * 32 + ((lane >> 3) & 1) * 8 + (lane & 7);   // + ng*16
    const int hi    = lane >> 4;                                          // chunk high bit
    const int swA   = (lrowA >> 1) & 3;
    const int swB   = (lrowB >> 1) & 3;

    float ca[4][4][4];
#pragma unroll
    for (int a = 0; a < 4; a++)
#pragma unroll
        for (int b = 0; b < 4; b++)
#pragma unroll
            for (int c = 0; c < 4; c++) ca[a][b][c] = 0.0f;

    // prologue: stage 0
    {
        cpasync16(sA0, gA); cpasync16(sA1, gA + 8);
        cpasync16(sB0, gB); cpasync16(sB1, gB + 8);
        asm volatile("cp.async.commit_group;");
    }

    for (int kt = 0; kt < 16; ++kt) {
        if (kt + 1 < 16) {
            const uint32_t off = (uint32_t)(((kt + 1) & 1) * 8192);
            const __nv_bfloat16* ga = gA + (kt + 1) * 32;
            const __nv_bfloat16* gb = gB + (kt + 1) * 32;
            cpasync16(sA0 + off, ga); cpasync16(sA1 + off, ga + 8);
            cpasync16(sB0 + off, gb); cpasync16(sB1 + off, gb + 8);
            asm volatile("cp.async.commit_group;");
            asm volatile("cp.async.wait_group 1;");
        } else {
            asm volatile("cp.async.wait_group 0;");
        }
        __syncthreads();

        const uint32_t boff = (uint32_t)((kt & 1) * 8192);
#pragma unroll
        for (int s = 0; s < 2; ++s) {
            uint32_t af[4][4], bfr[2][4];
#pragma unroll
            for (int mf = 0; mf < 4; ++mf) {
                uint32_t addr = aBase + boff + (uint32_t)((lrowA + mf * 16) * 64)
                              + (uint32_t)((((2 * s + hi) ^ swA)) * 16);
                ldsm4(af[mf], addr);
            }
#pragma unroll
            for (int ng = 0; ng < 2; ++ng) {
                uint32_t addr = bBase + boff + (uint32_t)((lrowB + ng * 16) * 64)
                              + (uint32_t)((((2 * s + hi) ^ swB)) * 16);
                ldsm4(bfr[ng], addr);
            }
#pragma unroll
            for (int mf = 0; mf < 4; ++mf)
#pragma unroll
                for (int nf = 0; nf < 4; ++nf) {
                    int ng = nf >> 1, u = nf & 1;
                    mma_bf16(ca[mf][nf], af[mf], bfr[ng][u], bfr[ng][2 + u]);
                }
        }
        __syncthreads();
    }

    // ---- fused epilogue: per-row online softmax + positive sums ----
    const float Cc = 14.4269504088896341f;   // 1/(T*ln2), T=0.1
    const int g  = lane >> 2;
    const int qq = lane & 3;
#pragma unroll
    for (int mf = 0; mf < 4; ++mf) {
#pragma unroll
        for (int h = 0; h < 2; ++h) {
            const int lrow = warp_m * 64 + mf * 16 + h * 8 + g;
            const int grow = row0 + lrow;
            const int rl = rlab_s[lrow];
            float tm = -1e30f, ps = 0.0f, cn = 0.0f;
            float sv[8];
#pragma unroll
            for (int nf = 0; nf < 4; ++nf) {
#pragma unroll
                for (int e = 0; e < 2; ++e) {
                    const int lcol = warp_n * 32 + nf * 8 + qq * 2 + e;
                    const float d = ca[mf][nf][h * 2 + e];
                    const bool diag = (grow == col0 + lcol);
                    const float s = diag ? -1e30f : d * Cc;
                    sv[nf * 2 + e] = s;
                    tm = fmaxf(tm, s);
                    if (!diag && clab_s[lcol] == rl) { ps += d; cn += 1.0f; }
                }
            }
            float l = 0.0f;
#pragma unroll
            for (int j = 0; j < 8; ++j) l += ex2f(sv[j] - tm);
            // merge across the 4 lanes of the quad (same row, different cols)
#pragma unroll
            for (int off = 1; off < 4; off <<= 1) {
                float mo = __shfl_xor_sync(0xFFFFFFFFu, tm, off);
                float lo = __shfl_xor_sync(0xFFFFFFFFu, l,  off);
                float po = __shfl_xor_sync(0xFFFFFFFFu, ps, off);
                float co = __shfl_xor_sync(0xFFFFFFFFu, cn, off);
                float mn = fmaxf(tm, mo);
                l = l * ex2f(tm - mn) + lo * ex2f(mo - mn);
                tm = mn; ps += po; cn += co;
            }
            if (qq == 0)
                g_part[J * 4 + warp_n][grow] = make_float4(tm, l, ps, cn);
        }
    }
}

// ---------------- final per-row merge + loss reduction ----------------
__global__ void __launch_bounds__(256)
supcon_reduce(float* __restrict__ out)
{
    const int row = blockIdx.x * 256 + threadIdx.x;
    float m = -1e30f, l = 0.0f, ps = 0.0f, cn = 0.0f;
#pragma unroll 4
    for (int s = 0; s < 256; ++s) {
        float4 p = g_part[s][row];
        float mn = fmaxf(m, p.x);
        l = l * ex2f(m - mn) + p.y * ex2f(p.x - mn);
        m = mn; ps += p.z; cn += p.w;
    }
    const float LN2 = 0.6931471805599453f;
    const float T = 0.1f;
    float contrib = (m + log2f(l)) * (LN2 * T / (float)NPTS) - ps / (cn * (float)NPTS);

    __shared__ float sred[8];
#pragma unroll
    for (int off = 16; off > 0; off >>= 1)
        contrib += __shfl_down_sync(0xFFFFFFFFu, contrib, off);
    if ((threadIdx.x & 31) == 0) sred[threadIdx.x >> 5] = contrib;
    __syncthreads();
    if (threadIdx.x < 8) {
        float v = sred[threadIdx.x];
#pragma unroll
        for (int off = 4; off > 0; off >>= 1)
            v += __shfl_down_sync(0xFFu, v, off);
        if (threadIdx.x == 0) atomicAdd(out, v);
    }
}

extern "C" void kernel_launch(void* const* d_in, const int* in_sizes, int n_in,
                              void* d_out, int out_size)
{
    const float*     emb    = (const float*)d_in[0];
    const long long* labels = (const long long*)d_in[1];
    float*           out    = (float*)d_out;

    conv_kernel<<<NPTS * DDIM / 8 / 256, 256>>>(emb);
    supcon_zero<<<1, 1>>>(out);
    dim3 grid(64, 64);
    supcon_gemm<<<grid, 256>>>(labels);
    supcon_reduce<<<NPTS / 256, 256>>>(out);
}

// round 4
// speedup vs baseline: 9.7298x; 1.6805x over previous
#include <cuda_runtime.h>
#include <cuda_bf16.h>
#include <cstdint>
#include <math.h>

// SupCon loss, N=8192, D=512, T=0.1
// bf16 mma.sync GEMM on upper-triangular tiles only (S symmetric),
// dual fused online-softmax epilogue (row-side + col-side), fast reduce.

#define NPTS 8192
#define DDIM 512
#define NBLK 64                 // 8192 / 128
#define NTILES_UT (NBLK * (NBLK + 1) / 2)   // 2080

__device__ __nv_bfloat16 g_ebf[NPTS * DDIM];     // 8 MB bf16 embeddings
__device__ float4 g_part[NBLK][NPTS];            // 8 MB partials: slot = other block idx

__device__ __forceinline__ uint32_t smem_u32(const void* p) {
    uint32_t a;
    asm("{ .reg .u64 t; cvta.to.shared.u64 t, %1; cvt.u32.u64 %0, t; }" : "=r"(a) : "l"(p));
    return a;
}
__device__ __forceinline__ float ex2f(float x) {
    float y; asm("ex2.approx.f32 %0, %1;" : "=f"(y) : "f"(x)); return y;
}
__device__ __forceinline__ void cpasync16(uint32_t saddr, const void* g) {
    asm volatile("cp.async.cg.shared.global [%0], [%1], 16;" :: "r"(saddr), "l"(g));
}
__device__ __forceinline__ void ldsm4(uint32_t* r, uint32_t addr) {
    asm volatile("ldmatrix.sync.aligned.m8n8.x4.shared.b16 {%0,%1,%2,%3}, [%4];"
                 : "=r"(r[0]), "=r"(r[1]), "=r"(r[2]), "=r"(r[3]) : "r"(addr));
}
__device__ __forceinline__ void mma_bf16(float* c, const uint32_t* a, uint32_t b0, uint32_t b1) {
    asm volatile("mma.sync.aligned.m16n8k16.row.col.f32.bf16.bf16.f32 "
                 "{%0,%1,%2,%3}, {%4,%5,%6,%7}, {%8,%9}, {%0,%1,%2,%3};"
                 : "+f"(c[0]), "+f"(c[1]), "+f"(c[2]), "+f"(c[3])
                 : "r"(a[0]), "r"(a[1]), "r"(a[2]), "r"(a[3]), "r"(b0), "r"(b1));
}

// ---------------- fp32 -> bf16 ----------------
__global__ void __launch_bounds__(256)
conv_kernel(const float* __restrict__ emb)
{
    int i = (blockIdx.x * 256 + threadIdx.x) * 8;
    float4 v0 = *reinterpret_cast<const float4*>(emb + i);
    float4 v1 = *reinterpret_cast<const float4*>(emb + i + 4);
    __nv_bfloat162 b0 = __float22bfloat162_rn(make_float2(v0.x, v0.y));
    __nv_bfloat162 b1 = __float22bfloat162_rn(make_float2(v0.z, v0.w));
    __nv_bfloat162 b2 = __float22bfloat162_rn(make_float2(v1.x, v1.y));
    __nv_bfloat162 b3 = __float22bfloat162_rn(make_float2(v1.z, v1.w));
    uint4 o;
    o.x = *reinterpret_cast<uint32_t*>(&b0);
    o.y = *reinterpret_cast<uint32_t*>(&b1);
    o.z = *reinterpret_cast<uint32_t*>(&b2);
    o.w = *reinterpret_cast<uint32_t*>(&b3);
    *reinterpret_cast<uint4*>(g_ebf + i) = o;
}

__global__ void supcon_zero(float* out) { *out = 0.0f; }

// ---------------- GEMM (upper-tri tiles) + dual fused epilogue ----------------
__global__ void __launch_bounds__(256, 2)
supcon_gemm(const long long* __restrict__ labels)
{
    __shared__ __align__(128) __nv_bfloat16 As[2][128 * 32];
    __shared__ __align__(128) __nv_bfloat16 Bs[2][128 * 32];
    __shared__ int rlab_s[128], clab_s[128];
    __shared__ __align__(16) float4 red_r[128 * 4];   // row-side: [row][warp_n]
    __shared__ __align__(16) float4 red_c[128 * 2];   // col-side: [col][warp_m]

    const int tid = threadIdx.x;
    const int wid = tid >> 5, lane = tid & 31;
    const int warp_m = wid >> 2, warp_n = wid & 3;

    // linear bid -> upper-triangular (I, J), I <= J
    int t = blockIdx.x, I = 0;
    while (t >= NBLK - I) { t -= NBLK - I; ++I; }
    const int J = I + t;
    const int row0 = I * 128, col0 = J * 128;
    const bool offdiag = (I != J);

    if (tid < 128) rlab_s[tid] = (int)labels[row0 + tid];
    else           clab_s[tid - 128] = (int)labels[col0 + tid - 128];

    const uint32_t aBase = smem_u32(As);
    const uint32_t bBase = smem_u32(Bs);

    const int ldr = tid >> 1;
    const int ldq = (tid & 1) * 2;
    const int ldsw = (ldr >> 1) & 3;
    const uint32_t sA0 = aBase + ldr * 64 + ((ldq ^ ldsw) * 16);
    const uint32_t sA1 = aBase + ldr * 64 + (((ldq + 1) ^ ldsw) * 16);
    const uint32_t sB0 = bBase + ldr * 64 + ((ldq ^ ldsw) * 16);
    const uint32_t sB1 = bBase + ldr * 64 + (((ldq + 1) ^ ldsw) * 16);
    const __nv_bfloat16* gA = g_ebf + (size_t)(row0 + ldr) * DDIM + ldq * 8;
    const __nv_bfloat16* gB = g_ebf + (size_t)(col0 + ldr) * DDIM + ldq * 8;

    const int lrowA = warp_m * 64 + ((lane >> 3) & 1) * 8 + (lane & 7);
    const int lrowB = warp_n * 32 + ((lane >> 3) & 1) * 8 + (lane & 7);
    const int hi    = lane >> 4;
    const int swA   = (lrowA >> 1) & 3;
    const int swB   = (lrowB >> 1) & 3;

    float ca[4][4][4];
#pragma unroll
    for (int a = 0; a < 4; a++)
#pragma unroll
        for (int b = 0; b < 4; b++)
#pragma unroll
            for (int c = 0; c < 4; c++) ca[a][b][c] = 0.0f;

    cpasync16(sA0, gA); cpasync16(sA1, gA + 8);
    cpasync16(sB0, gB); cpasync16(sB1, gB + 8);
    asm volatile("cp.async.commit_group;");

    for (int kt = 0; kt < 16; ++kt) {
        if (kt + 1 < 16) {
            const uint32_t off = (uint32_t)(((kt + 1) & 1) * 8192);
            const __nv_bfloat16* ga = gA + (kt + 1) * 32;
            const __nv_bfloat16* gb = gB + (kt + 1) * 32;
            cpasync16(sA0 + off, ga); cpasync16(sA1 + off, ga + 8);
            cpasync16(sB0 + off, gb); cpasync16(sB1 + off, gb + 8);
            asm volatile("cp.async.commit_group;");
            asm volatile("cp.async.wait_group 1;");
        } else {
            asm volatile("cp.async.wait_group 0;");
        }
        __syncthreads();

        const uint32_t boff = (uint32_t)((kt & 1) * 8192);
#pragma unroll
        for (int s = 0; s < 2; ++s) {
            uint32_t af[4][4], bfr[2][4];
#pragma unroll
            for (int mf = 0; mf < 4; ++mf)
                ldsm4(af[mf], aBase + boff + (uint32_t)((lrowA + mf * 16) * 64)
                               + (uint32_t)((((2 * s + hi) ^ swA)) * 16));
#pragma unroll
            for (int ng = 0; ng < 2; ++ng)
                ldsm4(bfr[ng], bBase + boff + (uint32_t)((lrowB + ng * 16) * 64)
                                + (uint32_t)((((2 * s + hi) ^ swB)) * 16));
#pragma unroll
            for (int mf = 0; mf < 4; ++mf)
#pragma unroll
                for (int nf = 0; nf < 4; ++nf) {
                    int ng = nf >> 1, u = nf & 1;
                    mma_bf16(ca[mf][nf], af[mf], bfr[ng][u], bfr[ng][2 + u]);
                }
        }
        __syncthreads();
    }

    const float Cc = 14.4269504088896341f;   // 1/(T*ln2), T=0.1
    const int g  = lane >> 2;
    const int qq = lane & 3;

    // ---- row-side: online state for rows of block I ----
#pragma unroll
    for (int mf = 0; mf < 4; ++mf) {
#pragma unroll
        for (int h = 0; h < 2; ++h) {
            const int lrow = warp_m * 64 + mf * 16 + h * 8 + g;
            const int grow = row0 + lrow;
            const int rl = rlab_s[lrow];
            float tm = -1e30f, ps = 0.0f, cn = 0.0f;
            float sv[8];
#pragma unroll
            for (int nf = 0; nf < 4; ++nf) {
#pragma unroll
                for (int e = 0; e < 2; ++e) {
                    const int lcol = warp_n * 32 + nf * 8 + qq * 2 + e;
                    const float d = ca[mf][nf][h * 2 + e];
                    const bool diag = (grow == col0 + lcol);   // only possible on diag tiles
                    const float s = diag ? -1e30f : d * Cc;
                    sv[nf * 2 + e] = s;
                    tm = fmaxf(tm, s);
                    if (!diag && clab_s[lcol] == rl) { ps += d; cn += 1.0f; }
                }
            }
            float l = 0.0f;
#pragma unroll
            for (int j = 0; j < 8; ++j) l += ex2f(sv[j] - tm);
#pragma unroll
            for (int off = 1; off < 4; off <<= 1) {
                float mo = __shfl_xor_sync(0xFFFFFFFFu, tm, off);
                float lo = __shfl_xor_sync(0xFFFFFFFFu, l,  off);
                float po = __shfl_xor_sync(0xFFFFFFFFu, ps, off);
                float co = __shfl_xor_sync(0xFFFFFFFFu, cn, off);
                float mn = fmaxf(tm, mo);
                l = l * ex2f(tm - mn) + lo * ex2f(mo - mn);
                tm = mn; ps += po; cn += co;
            }
            if (qq == 0) red_r[lrow * 4 + warp_n] = make_float4(tm, l, ps, cn);
        }
    }

    // ---- col-side (off-diagonal tiles): online state for rows of block J ----
    if (offdiag) {
#pragma unroll
        for (int nf = 0; nf < 4; ++nf) {
#pragma unroll
            for (int e = 0; e < 2; ++e) {
                const int lcol = warp_n * 32 + nf * 8 + qq * 2 + e;
                const int cl = clab_s[lcol];
                float tm = -1e30f, ps = 0.0f, cn = 0.0f;
                float sv[8];
#pragma unroll
                for (int mf = 0; mf < 4; ++mf) {
#pragma unroll
                    for (int h = 0; h < 2; ++h) {
                        const int lrow = warp_m * 64 + mf * 16 + h * 8 + g;
                        const float d = ca[mf][nf][h * 2 + e];
                        const float s = d * Cc;
                        sv[mf * 2 + h] = s;
                        tm = fmaxf(tm, s);
                        if (rlab_s[lrow] == cl) { ps += d; cn += 1.0f; }
                    }
                }
                float l = 0.0f;
#pragma unroll
                for (int j = 0; j < 8; ++j) l += ex2f(sv[j] - tm);
#pragma unroll
                for (int off = 4; off < 32; off <<= 1) {
                    float mo = __shfl_xor_sync(0xFFFFFFFFu, tm, off);
                    float lo = __shfl_xor_sync(0xFFFFFFFFu, l,  off);
                    float po = __shfl_xor_sync(0xFFFFFFFFu, ps, off);
                    float co = __shfl_xor_sync(0xFFFFFFFFu, cn, off);
                    float mn = fmaxf(tm, mo);
                    l = l * ex2f(tm - mn) + lo * ex2f(mo - mn);
                    tm = mn; ps += po; cn += co;
                }
                if (g == 0) red_c[lcol * 2 + warp_m] = make_float4(tm, l, ps, cn);
            }
        }
    }

    __syncthreads();

    // ---- final intra-CTA merges + partial writes ----
    if (tid < 128) {
        float4 p = red_r[tid * 4 + 0];
        float m = p.x, l = p.y, ps = p.z, cn = p.w;
#pragma unroll
        for (int s = 1; s < 4; ++s) {
            float4 q = red_r[tid * 4 + s];
            float mn = fmaxf(m, q.x);
            l = l * ex2f(m - mn) + q.y * ex2f(q.x - mn);
            m = mn; ps += q.z; cn += q.w;
        }
        g_part[J][row0 + tid] = make_float4(m, l, ps, cn);
    } else if (offdiag) {
        const int c = tid - 128;
        float4 p = red_c[c * 2 + 0];
        float4 q = red_c[c * 2 + 1];
        float mn = fmaxf(p.x, q.x);
        float l = p.y * ex2f(p.x - mn) + q.y * ex2f(q.x - mn);
        g_part[I][col0 + c] = make_float4(mn, l, p.z + q.z, p.w + q.w);
    }
}

// ---------------- final per-row merge + loss reduction ----------------
// 1 warp per row: 64 slots -> 2 per lane, shuffle-merge.
__global__ void __launch_bounds__(256)
supcon_reduce(float* __restrict__ out)
{
    const int wid = threadIdx.x >> 5, lane = threadIdx.x & 31;
    const int row = blockIdx.x * 8 + wid;

    float4 a = g_part[lane][row];
    float4 b = g_part[lane + 32][row];
    float m = fmaxf(a.x, b.x);
    float l = a.y * ex2f(a.x - m) + b.y * ex2f(b.x - m);
    float ps = a.z + b.z, cn = a.w + b.w;
#pragma unroll
    for (int off = 16; off > 0; off >>= 1) {
        float mo = __shfl_down_sync(0xFFFFFFFFu, m, off);
        float lo = __shfl_down_sync(0xFFFFFFFFu, l, off);
        float po = __shfl_down_sync(0xFFFFFFFFu, ps, off);
        float co = __shfl_down_sync(0xFFFFFFFFu, cn, off);
        float mn = fmaxf(m, mo);
        l = l * ex2f(m - mn) + lo * ex2f(mo - mn);
        m = mn; ps += po; cn += co;
    }

    __shared__ float sred[8];
    const float LN2 = 0.6931471805599453f;
    const float T = 0.1f;
    if (lane == 0)
        sred[wid] = (m + log2f(l)) * (LN2 * T / (float)NPTS) - ps / (cn * (float)NPTS);
    __syncthreads();
    if (threadIdx.x < 8) {
        float v = sred[threadIdx.x];
#pragma unroll
        for (int off = 4; off > 0; off >>= 1)
            v += __shfl_down_sync(0xFFu, v, off);
        if (threadIdx.x == 0) atomicAdd(out, v);
    }
}

extern "C" void kernel_launch(void* const* d_in, const int* in_sizes, int n_in,
                              void* d_out, int out_size)
{
    const float*     emb    = (const float*)d_in[0];
    const long long* labels = (const long long*)d_in[1];
    float*           out    = (float*)d_out;

    conv_kernel<<<NPTS * DDIM / 8 / 256, 256>>>(emb);
    supcon_zero<<<1, 1>>>(out);
    supcon_gemm<<<NTILES_UT, 256>>>(labels);
    supcon_reduce<<<NPTS / 8, 256>>>(out);
}

// round 6
// speedup vs baseline: 9.9397x; 1.0216x over previous
#include <cuda_runtime.h>
#include <cuda_bf16.h>
#include <cstdint>
#include <math.h>

// SupCon loss, N=8192, D=512, T=0.1
// bf16 mma.sync GEMM, upper-triangular tiles (S symmetric), dual fused
// max-first online-softmax epilogue. Round-4-proven 2-stage cp.async pipeline.

#define NPTS 8192
#define DDIM 512
#define NBLK 64
#define NTILES_UT (NBLK * (NBLK + 1) / 2)   // 2080
#define NOFFD (NBLK * (NBLK - 1) / 2)       // 2016

__device__ __nv_bfloat16 g_ebf[NPTS * DDIM];     // 8 MB bf16 embeddings
__device__ float4 g_part[NBLK][NPTS];            // 8 MB partials (w unused)
__device__ int g_hist[16];

__device__ __forceinline__ uint32_t smem_u32(const void* p) {
    uint32_t a;
    asm("{ .reg .u64 t; cvta.to.shared.u64 t, %1; cvt.u32.u64 %0, t; }" : "=r"(a) : "l"(p));
    return a;
}
__device__ __forceinline__ float ex2f(float x) {
    float y; asm("ex2.approx.f32 %0, %1;" : "=f"(y) : "f"(x)); return y;
}
__device__ __forceinline__ void cpasync16(uint32_t saddr, const void* g) {
    asm volatile("cp.async.cg.shared.global [%0], [%1], 16;" :: "r"(saddr), "l"(g));
}
__device__ __forceinline__ void ldsm4(uint32_t* r, uint32_t addr) {
    asm volatile("ldmatrix.sync.aligned.m8n8.x4.shared.b16 {%0,%1,%2,%3}, [%4];"
                 : "=r"(r[0]), "=r"(r[1]), "=r"(r[2]), "=r"(r[3]) : "r"(addr));
}
__device__ __forceinline__ void mma_bf16(float* c, const uint32_t* a, uint32_t b0, uint32_t b1) {
    asm volatile("mma.sync.aligned.m16n8k16.row.col.f32.bf16.bf16.f32 "
                 "{%0,%1,%2,%3}, {%4,%5,%6,%7}, {%8,%9}, {%0,%1,%2,%3};"
                 : "+f"(c[0]), "+f"(c[1]), "+f"(c[2]), "+f"(c[3])
                 : "r"(a[0]), "r"(a[1]), "r"(a[2]), "r"(a[3]), "r"(b0), "r"(b1));
}

// ---------------- fp32 -> bf16 ----------------
__global__ void __launch_bounds__(256)
conv_kernel(const float* __restrict__ emb)
{
    int i = (blockIdx.x * 256 + threadIdx.x) * 8;
    float4 v0 = *reinterpret_cast<const float4*>(emb + i);
    float4 v1 = *reinterpret_cast<const float4*>(emb + i + 4);
    __nv_bfloat162 b0 = __float22bfloat162_rn(make_float2(v0.x, v0.y));
    __nv_bfloat162 b1 = __float22bfloat162_rn(make_float2(v0.z, v0.w));
    __nv_bfloat162 b2 = __float22bfloat162_rn(make_float2(v1.x, v1.y));
    __nv_bfloat162 b3 = __float22bfloat162_rn(make_float2(v1.z, v1.w));
    uint4 o;
    o.x = *reinterpret_cast<uint32_t*>(&b0);
    o.y = *reinterpret_cast<uint32_t*>(&b1);
    o.z = *reinterpret_cast<uint32_t*>(&b2);
    o.w = *reinterpret_cast<uint32_t*>(&b3);
    *reinterpret_cast<uint4*>(g_ebf + i) = o;
}

__global__ void supcon_zero(float* out) {
    if (threadIdx.x == 0) *out = 0.0f;
    if (threadIdx.x < 16) g_hist[threadIdx.x] = 0;
}

__global__ void __launch_bounds__(256)
hist_kernel(const long long* __restrict__ labels)
{
    __shared__ int h[16];
    if (threadIdx.x < 16) h[threadIdx.x] = 0;
    __syncthreads();
    atomicAdd(&h[(int)labels[blockIdx.x * 256 + threadIdx.x]], 1);
    __syncthreads();
    if (threadIdx.x < 16) atomicAdd(&g_hist[threadIdx.x], h[threadIdx.x]);
}

// ---------------- GEMM (upper-tri tiles) + dual fused epilogue ----------------
__global__ void __launch_bounds__(256, 2)
supcon_gemm(const long long* __restrict__ labels)
{
    __shared__ __align__(128) __nv_bfloat16 As[2][128 * 32];
    __shared__ __align__(128) __nv_bfloat16 Bs[2][128 * 32];
    __shared__ int rlab_s[128], clab_s[128];
    __shared__ __align__(16) float4 red_r[128 * 4];   // row-side: [row][warp_n]
    __shared__ __align__(16) float4 red_c[128 * 2];   // col-side: [col][warp_m]

    const int tid = threadIdx.x;
    const int wid = tid >> 5, lane = tid & 31;
    const int warp_m = wid >> 2, warp_n = wid & 3;

    // bid -> (I,J): off-diagonal tiles first, diagonal tiles last (cheap tail)
    int I, J;
    if (blockIdx.x < NOFFD) {
        int q = blockIdx.x; I = 0;
        while (q >= NBLK - 1 - I) { q -= NBLK - 1 - I; ++I; }
        J = I + 1 + q;
    } else {
        I = J = blockIdx.x - NOFFD;
    }
    const int row0 = I * 128, col0 = J * 128;
    const bool offdiag = (I != J);

    if (tid < 128) rlab_s[tid] = (int)labels[row0 + tid];
    else           clab_s[tid - 128] = (int)labels[col0 + tid - 128];

    const uint32_t aBase = smem_u32(As);
    const uint32_t bBase = smem_u32(Bs);

    const int ldr = tid >> 1;
    const int ldq = (tid & 1) * 2;
    const int ldsw = (ldr >> 1) & 3;
    const uint32_t sA0 = aBase + ldr * 64 + ((ldq ^ ldsw) * 16);
    const uint32_t sA1 = aBase + ldr * 64 + (((ldq + 1) ^ ldsw) * 16);
    const uint32_t sB0 = bBase + ldr * 64 + ((ldq ^ ldsw) * 16);
    const uint32_t sB1 = bBase + ldr * 64 + (((ldq + 1) ^ ldsw) * 16);
    const __nv_bfloat16* gA = g_ebf + (size_t)(row0 + ldr) * DDIM + ldq * 8;
    const __nv_bfloat16* gB = g_ebf + (size_t)(col0 + ldr) * DDIM + ldq * 8;

    const int lrowA = warp_m * 64 + ((lane >> 3) & 1) * 8 + (lane & 7);
    const int lrowB = warp_n * 32 + ((lane >> 3) & 1) * 8 + (lane & 7);
    const int hi    = lane >> 4;
    const int swA   = (lrowA >> 1) & 3;
    const int swB   = (lrowB >> 1) & 3;

    float ca[4][4][4];
#pragma unroll
    for (int a = 0; a < 4; a++)
#pragma unroll
        for (int b = 0; b < 4; b++)
#pragma unroll
            for (int c = 0; c < 4; c++) ca[a][b][c] = 0.0f;

    cpasync16(sA0, gA); cpasync16(sA1, gA + 8);
    cpasync16(sB0, gB); cpasync16(sB1, gB + 8);
    asm volatile("cp.async.commit_group;");

    for (int kt = 0; kt < 16; ++kt) {
        if (kt + 1 < 16) {
            const uint32_t off = (uint32_t)(((kt + 1) & 1) * 8192);
            const __nv_bfloat16* ga = gA + (kt + 1) * 32;
            const __nv_bfloat16* gb = gB + (kt + 1) * 32;
            cpasync16(sA0 + off, ga); cpasync16(sA1 + off, ga + 8);
            cpasync16(sB0 + off, gb); cpasync16(sB1 + off, gb + 8);
            asm volatile("cp.async.commit_group;");
            asm volatile("cp.async.wait_group 1;");
        } else {
            asm volatile("cp.async.wait_group 0;");
        }
        __syncthreads();

        const uint32_t boff = (uint32_t)((kt & 1) * 8192);
#pragma unroll
        for (int s = 0; s < 2; ++s) {
            uint32_t af[4][4], bfr[2][4];
#pragma unroll
            for (int mf = 0; mf < 4; ++mf)
                ldsm4(af[mf], aBase + boff + (uint32_t)((lrowA + mf * 16) * 64)
                               + (uint32_t)((((2 * s + hi) ^ swA)) * 16));
#pragma unroll
            for (int ng = 0; ng < 2; ++ng)
                ldsm4(bfr[ng], bBase + boff + (uint32_t)((lrowB + ng * 16) * 64)
                                + (uint32_t)((((2 * s + hi) ^ swB)) * 16));
#pragma unroll
            for (int mf = 0; mf < 4; ++mf)
#pragma unroll
                for (int nf = 0; nf < 4; ++nf) {
                    int ng = nf >> 1, u = nf & 1;
                    mma_bf16(ca[mf][nf], af[mf], bfr[ng][u], bfr[ng][2 + u]);
                }
        }
        __syncthreads();
    }

    const float Cc = 14.4269504088896341f;   // 1/(T*ln2), T=0.1
    const int g  = lane >> 2;
    const int qq = lane & 3;

    // ---- row-side: max-first online state for rows of block I ----
#pragma unroll
    for (int mf = 0; mf < 4; ++mf) {
#pragma unroll
        for (int h = 0; h < 2; ++h) {
            const int lrow = warp_m * 64 + mf * 16 + h * 8 + g;
            const int grow = row0 + lrow;
            const int rl = rlab_s[lrow];
            float tm = -1e30f, ps = 0.0f;
#pragma unroll
            for (int nf = 0; nf < 4; ++nf)
#pragma unroll
                for (int e = 0; e < 2; ++e) {
                    const int lcol = warp_n * 32 + nf * 8 + qq * 2 + e;
                    const float d = ca[mf][nf][h * 2 + e];
                    const bool diag = (grow == col0 + lcol);
                    if (!diag) tm = fmaxf(tm, d * Cc);
                    if (!diag && clab_s[lcol] == rl) ps += d;
                }
            tm = fmaxf(tm, __shfl_xor_sync(0xFFFFFFFFu, tm, 1));
            tm = fmaxf(tm, __shfl_xor_sync(0xFFFFFFFFu, tm, 2));
            float l = 0.0f;
#pragma unroll
            for (int nf = 0; nf < 4; ++nf)
#pragma unroll
                for (int e = 0; e < 2; ++e) {
                    const int lcol = warp_n * 32 + nf * 8 + qq * 2 + e;
                    const bool diag = (grow == col0 + lcol);
                    if (!diag) l += ex2f(fmaf(ca[mf][nf][h * 2 + e], Cc, -tm));
                }
            l  += __shfl_xor_sync(0xFFFFFFFFu, l, 1);
            l  += __shfl_xor_sync(0xFFFFFFFFu, l, 2);
            ps += __shfl_xor_sync(0xFFFFFFFFu, ps, 1);
            ps += __shfl_xor_sync(0xFFFFFFFFu, ps, 2);
            if (qq == 0) red_r[lrow * 4 + warp_n] = make_float4(tm, l, ps, 0.0f);
        }
    }

    // ---- col-side (off-diagonal tiles): max-first state for rows of block J ----
    if (offdiag) {
#pragma unroll
        for (int nf = 0; nf < 4; ++nf)
#pragma unroll
            for (int e = 0; e < 2; ++e) {
                const int lcol = warp_n * 32 + nf * 8 + qq * 2 + e;
                const int cl = clab_s[lcol];
                float tm = -1e30f, ps = 0.0f;
#pragma unroll
                for (int mf = 0; mf < 4; ++mf)
#pragma unroll
                    for (int h = 0; h < 2; ++h) {
                        const float d = ca[mf][nf][h * 2 + e];
                        tm = fmaxf(tm, d * Cc);
                        if (rlab_s[warp_m * 64 + mf * 16 + h * 8 + g] == cl) ps += d;
                    }
                tm = fmaxf(tm, __shfl_xor_sync(0xFFFFFFFFu, tm, 4));
                tm = fmaxf(tm, __shfl_xor_sync(0xFFFFFFFFu, tm, 8));
                tm = fmaxf(tm, __shfl_xor_sync(0xFFFFFFFFu, tm, 16));
                float l = 0.0f;
#pragma unroll
                for (int mf = 0; mf < 4; ++mf)
#pragma unroll
                    for (int h = 0; h < 2; ++h)
                        l += ex2f(fmaf(ca[mf][nf][h * 2 + e], Cc, -tm));
                l  += __shfl_xor_sync(0xFFFFFFFFu, l, 4);
                l  += __shfl_xor_sync(0xFFFFFFFFu, l, 8);
                l  += __shfl_xor_sync(0xFFFFFFFFu, l, 16);
                ps += __shfl_xor_sync(0xFFFFFFFFu, ps, 4);
                ps += __shfl_xor_sync(0xFFFFFFFFu, ps, 8);
                ps += __shfl_xor_sync(0xFFFFFFFFu, ps, 16);
                if (g == 0) red_c[lcol * 2 + warp_m] = make_float4(tm, l, ps, 0.0f);
            }
    }

    __syncthreads();

    // ---- intra-CTA merges + partial writes ----
    if (tid < 128) {
        float4 p0 = red_r[tid * 4 + 0];
        float4 p1 = red_r[tid * 4 + 1];
        float4 p2 = red_r[tid * 4 + 2];
        float4 p3 = red_r[tid * 4 + 3];
        float m = fmaxf(fmaxf(p0.x, p1.x), fmaxf(p2.x, p3.x));
        float l = p0.y * ex2f(p0.x - m) + p1.y * ex2f(p1.x - m)
                + p2.y * ex2f(p2.x - m) + p3.y * ex2f(p3.x - m);
        g_part[J][row0 + tid] = make_float4(m, l, p0.z + p1.z + p2.z + p3.z, 0.0f);
    } else if (offdiag) {
        const int c = tid - 128;
        float4 p = red_c[c * 2 + 0];
        float4 q = red_c[c * 2 + 1];
        float mn = fmaxf(p.x, q.x);
        float l = p.y * ex2f(p.x - mn) + q.y * ex2f(q.x - mn);
        g_part[I][col0 + c] = make_float4(mn, l, p.z + q.z, 0.0f);
    }
}

// ---------------- final per-row merge + loss reduction ----------------
__global__ void __launch_bounds__(256)
supcon_reduce(const long long* __restrict__ labels, float* __restrict__ out)
{
    const int wid = threadIdx.x >> 5, lane = threadIdx.x & 31;
    const int row = blockIdx.x * 8 + wid;

    float4 a = g_part[lane][row];
    float4 b = g_part[lane + 32][row];
    float m = fmaxf(a.x, b.x);
    float l = a.y * ex2f(a.x - m) + b.y * ex2f(b.x - m);
    float ps = a.z + b.z;
#pragma unroll
    for (int off = 16; off > 0; off >>= 1) {
        float mo = __shfl_down_sync(0xFFFFFFFFu, m, off);
        float lo = __shfl_down_sync(0xFFFFFFFFu, l, off);
        float po = __shfl_down_sync(0xFFFFFFFFu, ps, off);
        float mn = fmaxf(m, mo);
        l = l * ex2f(m - mn) + lo * ex2f(mo - mn);
        m = mn; ps += po;
    }

    __shared__ float sred[8];
    const float LN2 = 0.6931471805599453f;
    const float T = 0.1f;
    if (lane == 0) {
        float cn = (float)(g_hist[(int)labels[row]] - 1);
        sred[wid] = (m + log2f(l)) * (LN2 * T / (float)NPTS) - ps / (cn * (float)NPTS);
    }
    __syncthreads();
    if (threadIdx.x < 8) {
        float v = sred[threadIdx.x];
#pragma unroll
        for (int off = 4; off > 0; off >>= 1)
            v += __shfl_down_sync(0xFFu, v, off);
        if (threadIdx.x == 0) atomicAdd(out, v);
    }
}

extern "C" void kernel_launch(void* const* d_in, const int* in_sizes, int n_in,
                              void* d_out, int out_size)
{
    const float*     emb    = (const float*)d_in[0];
    const long long* labels = (const long long*)d_in[1];
    float*           out    = (float*)d_out;

    supcon_zero<<<1, 32>>>(out);
    hist_kernel<<<NPTS / 256, 256>>>(labels);
    conv_kernel<<<NPTS * DDIM / 8 / 256, 256>>>(emb);
    supcon_gemm<<<NTILES_UT, 256>>>(labels);
    supcon_reduce<<<NPTS / 8, 256>>>(labels, out);
}

// round 7
// speedup vs baseline: 10.1569x; 1.0219x over previous
#include <cuda_runtime.h>
#include <cuda_bf16.h>
#include <cstdint>
#include <math.h>

// SupCon loss, N=8192, D=512, T=0.1
// bf16 mma.sync GEMM, upper-triangular tiles (S symmetric), dual fused
// max-first online-softmax epilogue. BK=64 stages, 2-stage double buffer.

#define NPTS 8192
#define DDIM 512
#define NBLK 64
#define NTILES_UT (NBLK * (NBLK + 1) / 2)   // 2080
#define NOFFD (NBLK * (NBLK - 1) / 2)       // 2016

// dynamic smem layout (bytes): tiles have 128B rows (full SW128 atom)
#define SM_A    0            // 2 stages x 16384
#define SM_B    32768        // 2 stages x 16384
#define SM_RLAB 65536        // 128 int
#define SM_CLAB 66048        // 128 int
#define SM_REDR 66560        // 512 float4 = 8192
#define SM_REDC 74752        // 256 float4 = 4096
#define SM_TOTAL 78848

__device__ __nv_bfloat16 g_ebf[NPTS * DDIM];     // 8 MB bf16 embeddings
__device__ float4 g_part[NBLK][NPTS];            // 8 MB partials
__device__ int g_hist[16];

__device__ __forceinline__ uint32_t smem_u32(const void* p) {
    uint32_t a;
    asm("{ .reg .u64 t; cvta.to.shared.u64 t, %1; cvt.u32.u64 %0, t; }" : "=r"(a) : "l"(p));
    return a;
}
__device__ __forceinline__ float ex2f(float x) {
    float y; asm("ex2.approx.f32 %0, %1;" : "=f"(y) : "f"(x)); return y;
}
__device__ __forceinline__ void cpasync16(uint32_t saddr, const void* g) {
    asm volatile("cp.async.cg.shared.global [%0], [%1], 16;" :: "r"(saddr), "l"(g));
}
__device__ __forceinline__ void ldsm4(uint32_t* r, uint32_t addr) {
    asm volatile("ldmatrix.sync.aligned.m8n8.x4.shared.b16 {%0,%1,%2,%3}, [%4];"
                 : "=r"(r[0]), "=r"(r[1]), "=r"(r[2]), "=r"(r[3]) : "r"(addr));
}
__device__ __forceinline__ void mma_bf16(float* c, const uint32_t* a, uint32_t b0, uint32_t b1) {
    asm volatile("mma.sync.aligned.m16n8k16.row.col.f32.bf16.bf16.f32 "
                 "{%0,%1,%2,%3}, {%4,%5,%6,%7}, {%8,%9}, {%0,%1,%2,%3};"
                 : "+f"(c[0]), "+f"(c[1]), "+f"(c[2]), "+f"(c[3])
                 : "r"(a[0]), "r"(a[1]), "r"(a[2]), "r"(a[3]), "r"(b0), "r"(b1));
}

// ---------------- fp32 -> bf16 ----------------
__global__ void __launch_bounds__(256)
conv_kernel(const float* __restrict__ emb)
{
    int i = (blockIdx.x * 256 + threadIdx.x) * 8;
    float4 v0 = *reinterpret_cast<const float4*>(emb + i);
    float4 v1 = *reinterpret_cast<const float4*>(emb + i + 4);
    __nv_bfloat162 b0 = __float22bfloat162_rn(make_float2(v0.x, v0.y));
    __nv_bfloat162 b1 = __float22bfloat162_rn(make_float2(v0.z, v0.w));
    __nv_bfloat162 b2 = __float22bfloat162_rn(make_float2(v1.x, v1.y));
    __nv_bfloat162 b3 = __float22bfloat162_rn(make_float2(v1.z, v1.w));
    uint4 o;
    o.x = *reinterpret_cast<uint32_t*>(&b0);
    o.y = *reinterpret_cast<uint32_t*>(&b1);
    o.z = *reinterpret_cast<uint32_t*>(&b2);
    o.w = *reinterpret_cast<uint32_t*>(&b3);
    *reinterpret_cast<uint4*>(g_ebf + i) = o;
}

__global__ void supcon_zero(float* out) {
    if (threadIdx.x == 0) *out = 0.0f;
    if (threadIdx.x < 16) g_hist[threadIdx.x] = 0;
}

__global__ void __launch_bounds__(256)
hist_kernel(const long long* __restrict__ labels)
{
    __shared__ int h[16];
    if (threadIdx.x < 16) h[threadIdx.x] = 0;
    __syncthreads();
    atomicAdd(&h[(int)labels[blockIdx.x * 256 + threadIdx.x]], 1);
    __syncthreads();
    if (threadIdx.x < 16) atomicAdd(&g_hist[threadIdx.x], h[threadIdx.x]);
}

// ---------------- GEMM (upper-tri tiles) + dual fused epilogue ----------------
__global__ void __launch_bounds__(256, 2)
supcon_gemm(const long long* __restrict__ labels)
{
    extern __shared__ __align__(128) char smem[];
    int* rlab_s = (int*)(smem + SM_RLAB);
    int* clab_s = (int*)(smem + SM_CLAB);
    float4* red_r = (float4*)(smem + SM_REDR);
    float4* red_c = (float4*)(smem + SM_REDC);

    const int tid = threadIdx.x;
    const int wid = tid >> 5, lane = tid & 31;
    const int warp_m = wid >> 2, warp_n = wid & 3;

    // bid -> (I,J): off-diagonal tiles first, diagonal tiles last (cheap tail)
    int I, J;
    if (blockIdx.x < NOFFD) {
        int q = blockIdx.x; I = 0;
        while (q >= NBLK - 1 - I) { q -= NBLK - 1 - I; ++I; }
        J = I + 1 + q;
    } else {
        I = J = blockIdx.x - NOFFD;
    }
    const int row0 = I * 128, col0 = J * 128;
    const bool offdiag = (I != J);

    if (tid < 128) rlab_s[tid] = (int)labels[row0 + tid];
    else           clab_s[tid - 128] = (int)labels[col0 + tid - 128];

    const uint32_t aBase = smem_u32(smem + SM_A);
    const uint32_t bBase = smem_u32(smem + SM_B);

    // ---- cp.async mapping: row = tid>>1, half = tid&1 (4 x 16B = 64B contiguous) ----
    const int ldr = tid >> 1;
    const int ldh = tid & 1;
    const int swl = ldr & 7;
    uint32_t stA[4], stB[4];
#pragma unroll
    for (int j = 0; j < 4; ++j) {
        const uint32_t off = (uint32_t)(ldr * 128 + (((ldh * 4 + j) ^ swl) * 16));
        stA[j] = aBase + off;
        stB[j] = bBase + off;
    }
    const __nv_bfloat16* gA = g_ebf + (size_t)(row0 + ldr) * DDIM + ldh * 32;
    const __nv_bfloat16* gB = g_ebf + (size_t)(col0 + ldr) * DDIM + ldh * 32;

    // ---- ldmatrix addressing: 128B rows, chunk = (2s+hi) ^ (row&7) ----
    const int lrowA = warp_m * 64 + ((lane >> 3) & 1) * 8 + (lane & 7);
    const int lrowB = warp_n * 32 + ((lane >> 3) & 1) * 8 + (lane & 7);
    const int hi    = lane >> 4;
    const uint32_t rowA = aBase + (uint32_t)(lrowA * 128);
    const uint32_t rowB = bBase + (uint32_t)(lrowB * 128);
    uint32_t colA[4], colB[4];
#pragma unroll
    for (int s = 0; s < 4; ++s) {
        colA[s] = (uint32_t)((((2 * s + hi) ^ (lrowA & 7))) * 16);
        colB[s] = (uint32_t)((((2 * s + hi) ^ (lrowB & 7))) * 16);
    }

    float ca[4][4][4];
#pragma unroll
    for (int a = 0; a < 4; a++)
#pragma unroll
        for (int b = 0; b < 4; b++)
#pragma unroll
            for (int c = 0; c < 4; c++) ca[a][b][c] = 0.0f;

    // prologue: stage 0
#pragma unroll
    for (int j = 0; j < 4; ++j) {
        cpasync16(stA[j], gA + j * 8);
        cpasync16(stB[j], gB + j * 8);
    }
    asm volatile("cp.async.commit_group;");

    for (int kt = 0; kt < 8; ++kt) {
        if (kt + 1 < 8) {
            const uint32_t off = (uint32_t)(((kt + 1) & 1) * 16384);
            const __nv_bfloat16* ga = gA + (kt + 1) * 64;
            const __nv_bfloat16* gb = gB + (kt + 1) * 64;
#pragma unroll
            for (int j = 0; j < 4; ++j) {
                cpasync16(stA[j] + off, ga + j * 8);
                cpasync16(stB[j] + off, gb + j * 8);
            }
            asm volatile("cp.async.commit_group;");
            asm volatile("cp.async.wait_group 1;");
        } else {
            asm volatile("cp.async.wait_group 0;");
        }
        __syncthreads();

        const uint32_t boff = (uint32_t)((kt & 1) * 16384);
#pragma unroll
        for (int s = 0; s < 4; ++s) {
            uint32_t af[4][4], bfr[2][4];
#pragma unroll
            for (int mf = 0; mf < 4; ++mf)
                ldsm4(af[mf], rowA + boff + colA[s] + (uint32_t)(mf * 2048));
#pragma unroll
            for (int ng = 0; ng < 2; ++ng)
                ldsm4(bfr[ng], rowB + boff + colB[s] + (uint32_t)(ng * 2048));
#pragma unroll
            for (int mf = 0; mf < 4; ++mf)
#pragma unroll
                for (int nf = 0; nf < 4; ++nf) {
                    int ng = nf >> 1, u = nf & 1;
                    mma_bf16(ca[mf][nf], af[mf], bfr[ng][u], bfr[ng][2 + u]);
                }
        }
        __syncthreads();
    }

    const float Cc = 14.4269504088896341f;   // 1/(T*ln2), T=0.1
    const int g  = lane >> 2;
    const int qq = lane & 3;

    // ---- row-side: max-first online state for rows of block I ----
#pragma unroll
    for (int mf = 0; mf < 4; ++mf) {
#pragma unroll
        for (int h = 0; h < 2; ++h) {
            const int lrow = warp_m * 64 + mf * 16 + h * 8 + g;
            const int grow = row0 + lrow;
            const int rl = rlab_s[lrow];
            float tm = -1e30f, ps = 0.0f;
#pragma unroll
            for (int nf = 0; nf < 4; ++nf)
#pragma unroll
                for (int e = 0; e < 2; ++e) {
                    const int lcol = warp_n * 32 + nf * 8 + qq * 2 + e;
                    const float d = ca[mf][nf][h * 2 + e];
                    const bool diag = (grow == col0 + lcol);
                    if (!diag) tm = fmaxf(tm, d * Cc);
                    if (!diag && clab_s[lcol] == rl) ps += d;
                }
            tm = fmaxf(tm, __shfl_xor_sync(0xFFFFFFFFu, tm, 1));
            tm = fmaxf(tm, __shfl_xor_sync(0xFFFFFFFFu, tm, 2));
            float l = 0.0f;
#pragma unroll
            for (int nf = 0; nf < 4; ++nf)
#pragma unroll
                for (int e = 0; e < 2; ++e) {
                    const int lcol = warp_n * 32 + nf * 8 + qq * 2 + e;
                    const bool diag = (grow == col0 + lcol);
                    if (!diag) l += ex2f(fmaf(ca[mf][nf][h * 2 + e], Cc, -tm));
                }
            l  += __shfl_xor_sync(0xFFFFFFFFu, l, 1);
            l  += __shfl_xor_sync(0xFFFFFFFFu, l, 2);
            ps += __shfl_xor_sync(0xFFFFFFFFu, ps, 1);
            ps += __shfl_xor_sync(0xFFFFFFFFu, ps, 2);
            if (qq == 0) red_r[lrow * 4 + warp_n] = make_float4(tm, l, ps, 0.0f);
        }
    }

    // ---- col-side (off-diagonal tiles): max-first state for rows of block J ----
    if (offdiag) {
#pragma unroll
        for (int nf = 0; nf < 4; ++nf)
#pragma unroll
            for (int e = 0; e < 2; ++e) {
                const int lcol = warp_n * 32 + nf * 8 + qq * 2 + e;
                const int cl = clab_s[lcol];
                float tm = -1e30f, ps = 0.0f;
#pragma unroll
                for (int mf = 0; mf < 4; ++mf)
#pragma unroll
                    for (int h = 0; h < 2; ++h) {
                        const float d = ca[mf][nf][h * 2 + e];
                        tm = fmaxf(tm, d * Cc);
                        if (rlab_s[warp_m * 64 + mf * 16 + h * 8 + g] == cl) ps += d;
                    }
                tm = fmaxf(tm, __shfl_xor_sync(0xFFFFFFFFu, tm, 4));
                tm = fmaxf(tm, __shfl_xor_sync(0xFFFFFFFFu, tm, 8));
                tm = fmaxf(tm, __shfl_xor_sync(0xFFFFFFFFu, tm, 16));
                float l = 0.0f;
#pragma unroll
                for (int mf = 0; mf < 4; ++mf)
#pragma unroll
                    for (int h = 0; h < 2; ++h)
                        l += ex2f(fmaf(ca[mf][nf][h * 2 + e], Cc, -tm));
                l  += __shfl_xor_sync(0xFFFFFFFFu, l, 4);
                l  += __shfl_xor_sync(0xFFFFFFFFu, l, 8);
                l  += __shfl_xor_sync(0xFFFFFFFFu, l, 16);
                ps += __shfl_xor_sync(0xFFFFFFFFu, ps, 4);
                ps += __shfl_xor_sync(0xFFFFFFFFu, ps, 8);
                ps += __shfl_xor_sync(0xFFFFFFFFu, ps, 16);
                if (g == 0) red_c[lcol * 2 + warp_m] = make_float4(tm, l, ps, 0.0f);
            }
    }

    __syncthreads();

    // ---- intra-CTA merges + partial writes ----
    if (tid < 128) {
        float4 p0 = red_r[tid * 4 + 0];
        float4 p1 = red_r[tid * 4 + 1];
        float4 p2 = red_r[tid * 4 + 2];
        float4 p3 = red_r[tid * 4 + 3];
        float m = fmaxf(fmaxf(p0.x, p1.x), fmaxf(p2.x, p3.x));
        float l = p0.y * ex2f(p0.x - m) + p1.y * ex2f(p1.x - m)
                + p2.y * ex2f(p2.x - m) + p3.y * ex2f(p3.x - m);
        g_part[J][row0 + tid] = make_float4(m, l, p0.z + p1.z + p2.z + p3.z, 0.0f);
    } else if (offdiag) {
        const int c = tid - 128;
        float4 p = red_c[c * 2 + 0];
        float4 q = red_c[c * 2 + 1];
        float mn = fmaxf(p.x, q.x);
        float l = p.y * ex2f(p.x - mn) + q.y * ex2f(q.x - mn);
        g_part[I][col0 + c] = make_float4(mn, l, p.z + q.z, 0.0f);
    }
}

// ---------------- final per-row merge + loss reduction ----------------
__global__ void __launch_bounds__(256)
supcon_reduce(const long long* __restrict__ labels, float* __restrict__ out)
{
    const int wid = threadIdx.x >> 5, lane = threadIdx.x & 31;
    const int row = blockIdx.x * 8 + wid;

    float4 a = g_part[lane][row];
    float4 b = g_part[lane + 32][row];
    float m = fmaxf(a.x, b.x);
    float l = a.y * ex2f(a.x - m) + b.y * ex2f(b.x - m);
    float ps = a.z + b.z;
#pragma unroll
    for (int off = 16; off > 0; off >>= 1) {
        float mo = __shfl_down_sync(0xFFFFFFFFu, m, off);
        float lo = __shfl_down_sync(0xFFFFFFFFu, l, off);
        float po = __shfl_down_sync(0xFFFFFFFFu, ps, off);
        float mn = fmaxf(m, mo);
        l = l * ex2f(m - mn) + lo * ex2f(mo - mn);
        m = mn; ps += po;
    }

    __shared__ float sred[8];
    const float LN2 = 0.6931471805599453f;
    const float T = 0.1f;
    if (lane == 0) {
        float cn = (float)(g_hist[(int)labels[row]] - 1);
        sred[wid] = (m + log2f(l)) * (LN2 * T / (float)NPTS) - ps / (cn * (float)NPTS);
    }
    __syncthreads();
    if (threadIdx.x < 8) {
        float v = sred[threadIdx.x];
#pragma unroll
        for (int off = 4; off > 0; off >>= 1)
            v += __shfl_down_sync(0xFFu, v, off);
        if (threadIdx.x == 0) atomicAdd(out, v);
    }
}

extern "C" void kernel_launch(void* const* d_in, const int* in_sizes, int n_in,
                              void* d_out, int out_size)
{
    const float*     emb    = (const float*)d_in[0];
    const long long* labels = (const long long*)d_in[1];
    float*           out    = (float*)d_out;

    static int configured = 0;
    cudaFuncSetAttribute(supcon_gemm, cudaFuncAttributeMaxDynamicSharedMemorySize, SM_TOTAL);
    (void)configured;

    supcon_zero<<<1, 32>>>(out);
    hist_kernel<<<NPTS / 256, 256>>>(labels);
    conv_kernel<<<NPTS * DDIM / 8 / 256, 256>>>(emb);
    supcon_gemm<<<NTILES_UT, 256, SM_TOTAL>>>(labels);
    supcon_reduce<<<NPTS / 8, 256>>>(labels, out);
}

// round 8
// speedup vs baseline: 10.1719x; 1.0015x over previous
#include <cuda_runtime.h>
#include <cuda_bf16.h>
#include <cstdint>
#include <math.h>

// SupCon loss, N=8192, D=512, T=0.1
// bf16 mma.sync GEMM, upper-triangular tiles (S symmetric), dual fused
// max-first online-softmax epilogue. BK=64 stages, 2-stage double buffer.

#define NPTS 8192
#define DDIM 512
#define NBLK 64
#define NTILES_UT (NBLK * (NBLK + 1) / 2)   // 2080
#define NOFFD (NBLK * (NBLK - 1) / 2)       // 2016

// dynamic smem layout (bytes): tiles have 128B rows (full SW128 atom)
#define SM_A    0            // 2 stages x 16384
#define SM_B    32768        // 2 stages x 16384
#define SM_RLAB 65536        // 128 int
#define SM_CLAB 66048        // 128 int
#define SM_REDR 66560        // 512 float4 = 8192
#define SM_REDC 74752        // 256 float4 = 4096
#define SM_TOTAL 78848

__device__ __nv_bfloat16 g_ebf[NPTS * DDIM];     // 8 MB bf16 embeddings
__device__ float4 g_part[NBLK][NPTS];            // 8 MB partials
__device__ int g_hist[16];

__device__ __forceinline__ uint32_t smem_u32(const void* p) {
    uint32_t a;
    asm("{ .reg .u64 t; cvta.to.shared.u64 t, %1; cvt.u32.u64 %0, t; }" : "=r"(a) : "l"(p));
    return a;
}
__device__ __forceinline__ float ex2f(float x) {
    float y; asm("ex2.approx.f32 %0, %1;" : "=f"(y) : "f"(x)); return y;
}
__device__ __forceinline__ void cpasync16(uint32_t saddr, const void* g) {
    asm volatile("cp.async.cg.shared.global [%0], [%1], 16;" :: "r"(saddr), "l"(g));
}
__device__ __forceinline__ void ldsm4(uint32_t* r, uint32_t addr) {
    asm volatile("ldmatrix.sync.aligned.m8n8.x4.shared.b16 {%0,%1,%2,%3}, [%4];"
                 : "=r"(r[0]), "=r"(r[1]), "=r"(r[2]), "=r"(r[3]) : "r"(addr));
}
__device__ __forceinline__ void mma_bf16(float* c, const uint32_t* a, uint32_t b0, uint32_t b1) {
    asm volatile("mma.sync.aligned.m16n8k16.row.col.f32.bf16.bf16.f32 "
                 "{%0,%1,%2,%3}, {%4,%5,%6,%7}, {%8,%9}, {%0,%1,%2,%3};"
                 : "+f"(c[0]), "+f"(c[1]), "+f"(c[2]), "+f"(c[3])
                 : "r"(a[0]), "r"(a[1]), "r"(a[2]), "r"(a[3]), "r"(b0), "r"(b1));
}

// ---------------- fp32 -> bf16 ----------------
__global__ void __launch_bounds__(256)
conv_kernel(const float* __restrict__ emb)
{
    int i = (blockIdx.x * 256 + threadIdx.x) * 8;
    float4 v0 = *reinterpret_cast<const float4*>(emb + i);
    float4 v1 = *reinterpret_cast<const float4*>(emb + i + 4);
    __nv_bfloat162 b0 = __float22bfloat162_rn(make_float2(v0.x, v0.y));
    __nv_bfloat162 b1 = __float22bfloat162_rn(make_float2(v0.z, v0.w));
    __nv_bfloat162 b2 = __float22bfloat162_rn(make_float2(v1.x, v1.y));
    __nv_bfloat162 b3 = __float22bfloat162_rn(make_float2(v1.z, v1.w));
    uint4 o;
    o.x = *reinterpret_cast<uint32_t*>(&b0);
    o.y = *reinterpret_cast<uint32_t*>(&b1);
    o.z = *reinterpret_cast<uint32_t*>(&b2);
    o.w = *reinterpret_cast<uint32_t*>(&b3);
    *reinterpret_cast<uint4*>(g_ebf + i) = o;
}

__global__ void supcon_zero(float* out) {
    if (threadIdx.x == 0) *out = 0.0f;
    if (threadIdx.x < 16) g_hist[threadIdx.x] = 0;
}

__global__ void __launch_bounds__(256)
hist_kernel(const long long* __restrict__ labels)
{
    __shared__ int h[16];
    if (threadIdx.x < 16) h[threadIdx.x] = 0;
    __syncthreads();
    atomicAdd(&h[(int)labels[blockIdx.x * 256 + threadIdx.x]], 1);
    __syncthreads();
    if (threadIdx.x < 16) atomicAdd(&g_hist[threadIdx.x], h[threadIdx.x]);
}

// ---------------- GEMM (upper-tri tiles) + dual fused epilogue ----------------
__global__ void __launch_bounds__(256, 2)
supcon_gemm(const long long* __restrict__ labels)
{
    extern __shared__ __align__(128) char smem[];
    int* rlab_s = (int*)(smem + SM_RLAB);
    int* clab_s = (int*)(smem + SM_CLAB);
    float4* red_r = (float4*)(smem + SM_REDR);
    float4* red_c = (float4*)(smem + SM_REDC);

    const int tid = threadIdx.x;
    const int wid = tid >> 5, lane = tid & 31;
    const int warp_m = wid >> 2, warp_n = wid & 3;

    // bid -> (I,J): off-diagonal tiles first, diagonal tiles last (cheap tail)
    int I, J;
    if (blockIdx.x < NOFFD) {
        int q = blockIdx.x; I = 0;
        while (q >= NBLK - 1 - I) { q -= NBLK - 1 - I; ++I; }
        J = I + 1 + q;
    } else {
        I = J = blockIdx.x - NOFFD;
    }
    const int row0 = I * 128, col0 = J * 128;
    const bool offdiag = (I != J);

    if (tid < 128) rlab_s[tid] = (int)labels[row0 + tid];
    else           clab_s[tid - 128] = (int)labels[col0 + tid - 128];

    const uint32_t aBase = smem_u32(smem + SM_A);
    const uint32_t bBase = smem_u32(smem + SM_B);

    // ---- cp.async mapping: row = tid>>1, half = tid&1 (4 x 16B = 64B contiguous) ----
    const int ldr = tid >> 1;
    const int ldh = tid & 1;
    const int swl = ldr & 7;
    uint32_t stA[4], stB[4];
#pragma unroll
    for (int j = 0; j < 4; ++j) {
        const uint32_t off = (uint32_t)(ldr * 128 + (((ldh * 4 + j) ^ swl) * 16));
        stA[j] = aBase + off;
        stB[j] = bBase + off;
    }
    const __nv_bfloat16* gA = g_ebf + (size_t)(row0 + ldr) * DDIM + ldh * 32;
    const __nv_bfloat16* gB = g_ebf + (size_t)(col0 + ldr) * DDIM + ldh * 32;

    // ---- ldmatrix addressing: 128B rows, chunk = (2s+hi) ^ (row&7) ----
    const int lrowA = warp_m * 64 + ((lane >> 3) & 1) * 8 + (lane & 7);
    const int lrowB = warp_n * 32 + ((lane >> 3) & 1) * 8 + (lane & 7);
    const int hi    = lane >> 4;
    const uint32_t rowA = aBase + (uint32_t)(lrowA * 128);
    const uint32_t rowB = bBase + (uint32_t)(lrowB * 128);
    uint32_t colA[4], colB[4];
#pragma unroll
    for (int s = 0; s < 4; ++s) {
        colA[s] = (uint32_t)((((2 * s + hi) ^ (lrowA & 7))) * 16);
        colB[s] = (uint32_t)((((2 * s + hi) ^ (lrowB & 7))) * 16);
    }

    float ca[4][4][4];
#pragma unroll
    for (int a = 0; a < 4; a++)
#pragma unroll
        for (int b = 0; b < 4; b++)
#pragma unroll
            for (int c = 0; c < 4; c++) ca[a][b][c] = 0.0f;

    // prologue: stage 0
#pragma unroll
    for (int j = 0; j < 4; ++j) {
        cpasync16(stA[j], gA + j * 8);
        cpasync16(stB[j], gB + j * 8);
    }
    asm volatile("cp.async.commit_group;");

    for (int kt = 0; kt < 8; ++kt) {
        if (kt + 1 < 8) {
            const uint32_t off = (uint32_t)(((kt + 1) & 1) * 16384);
            const __nv_bfloat16* ga = gA + (kt + 1) * 64;
            const __nv_bfloat16* gb = gB + (kt + 1) * 64;
#pragma unroll
            for (int j = 0; j < 4; ++j) {
                cpasync16(stA[j] + off, ga + j * 8);
                cpasync16(stB[j] + off, gb + j * 8);
            }
            asm volatile("cp.async.commit_group;");
            asm volatile("cp.async.wait_group 1;");
        } else {
            asm volatile("cp.async.wait_group 0;");
        }
        __syncthreads();

        const uint32_t boff = (uint32_t)((kt & 1) * 16384);
#pragma unroll
        for (int s = 0; s < 4; ++s) {
            uint32_t af[4][4], bfr[2][4];
#pragma unroll
            for (int mf = 0; mf < 4; ++mf)
                ldsm4(af[mf], rowA + boff + colA[s] + (uint32_t)(mf * 2048));
#pragma unroll
            for (int ng = 0; ng < 2; ++ng)
                ldsm4(bfr[ng], rowB + boff + colB[s] + (uint32_t)(ng * 2048));
#pragma unroll
            for (int mf = 0; mf < 4; ++mf)
#pragma unroll
                for (int nf = 0; nf < 4; ++nf) {
                    int ng = nf >> 1, u = nf & 1;
                    mma_bf16(ca[mf][nf], af[mf], bfr[ng][u], bfr[ng][2 + u]);
                }
        }
        __syncthreads();
    }

    const float Cc = 14.4269504088896341f;   // 1/(T*ln2), T=0.1
    const int g  = lane >> 2;
    const int qq = lane & 3;

    // ---- row-side: max-first online state for rows of block I ----
#pragma unroll
    for (int mf = 0; mf < 4; ++mf) {
#pragma unroll
        for (int h = 0; h < 2; ++h) {
            const int lrow = warp_m * 64 + mf * 16 + h * 8 + g;
            const int grow = row0 + lrow;
            const int rl = rlab_s[lrow];
            float tm = -1e30f, ps = 0.0f;
#pragma unroll
            for (int nf = 0; nf < 4; ++nf)
#pragma unroll
                for (int e = 0; e < 2; ++e) {
                    const int lcol = warp_n * 32 + nf * 8 + qq * 2 + e;
                    const float d = ca[mf][nf][h * 2 + e];
                    const bool diag = (grow == col0 + lcol);
                    if (!diag) tm = fmaxf(tm, d * Cc);
                    if (!diag && clab_s[lcol] == rl) ps += d;
                }
            tm = fmaxf(tm, __shfl_xor_sync(0xFFFFFFFFu, tm, 1));
            tm = fmaxf(tm, __shfl_xor_sync(0xFFFFFFFFu, tm, 2));
            float l = 0.0f;
#pragma unroll
            for (int nf = 0; nf < 4; ++nf)
#pragma unroll
                for (int e = 0; e < 2; ++e) {
                    const int lcol = warp_n * 32 + nf * 8 + qq * 2 + e;
                    const bool diag = (grow == col0 + lcol);
                    if (!diag) l += ex2f(fmaf(ca[mf][nf][h * 2 + e], Cc, -tm));
                }
            l  += __shfl_xor_sync(0xFFFFFFFFu, l, 1);
            l  += __shfl_xor_sync(0xFFFFFFFFu, l, 2);
            ps += __shfl_xor_sync(0xFFFFFFFFu, ps, 1);
            ps += __shfl_xor_sync(0xFFFFFFFFu, ps, 2);
            if (qq == 0) red_r[lrow * 4 + warp_n] = make_float4(tm, l, ps, 0.0f);
        }
    }

    // ---- col-side (off-diagonal tiles): max-first state for rows of block J ----
    if (offdiag) {
#pragma unroll
        for (int nf = 0; nf < 4; ++nf)
#pragma unroll
            for (int e = 0; e < 2; ++e) {
                const int lcol = warp_n * 32 + nf * 8 + qq * 2 + e;
                const int cl = clab_s[lcol];
                float tm = -1e30f, ps = 0.0f;
#pragma unroll
                for (int mf = 0; mf < 4; ++mf)
#pragma unroll
                    for (int h = 0; h < 2; ++h) {
                        const float d = ca[mf][nf][h * 2 + e];
                        tm = fmaxf(tm, d * Cc);
                        if (rlab_s[warp_m * 64 + mf * 16 + h * 8 + g] == cl) ps += d;
                    }
                tm = fmaxf(tm, __shfl_xor_sync(0xFFFFFFFFu, tm, 4));
                tm = fmaxf(tm, __shfl_xor_sync(0xFFFFFFFFu, tm, 8));
                tm = fmaxf(tm, __shfl_xor_sync(0xFFFFFFFFu, tm, 16));
                float l = 0.0f;
#pragma unroll
                for (int mf = 0; mf < 4; ++mf)
#pragma unroll
                    for (int h = 0; h < 2; ++h)
                        l += ex2f(fmaf(ca[mf][nf][h * 2 + e], Cc, -tm));
                l  += __shfl_xor_sync(0xFFFFFFFFu, l, 4);
                l  += __shfl_xor_sync(0xFFFFFFFFu, l, 8);
                l  += __shfl_xor_sync(0xFFFFFFFFu, l, 16);
                ps += __shfl_xor_sync(0xFFFFFFFFu, ps, 4);
                ps += __shfl_xor_sync(0xFFFFFFFFu, ps, 8);
                ps += __shfl_xor_sync(0xFFFFFFFFu, ps, 16);
                if (g == 0) red_c[lcol * 2 + warp_m] = make_float4(tm, l, ps, 0.0f);
            }
    }

    __syncthreads();

    // ---- intra-CTA merges + partial writes ----
    if (tid < 128) {
        float4 p0 = red_r[tid * 4 + 0];
        float4 p1 = red_r[tid * 4 + 1];
        float4 p2 = red_r[tid * 4 + 2];
        float4 p3 = red_r[tid * 4 + 3];
        float m = fmaxf(fmaxf(p0.x, p1.x), fmaxf(p2.x, p3.x));
        float l = p0.y * ex2f(p0.x - m) + p1.y * ex2f(p1.x - m)
                + p2.y * ex2f(p2.x - m) + p3.y * ex2f(p3.x - m);
        g_part[J][row0 + tid] = make_float4(m, l, p0.z + p1.z + p2.z + p3.z, 0.0f);
    } else if (offdiag) {
        const int c = tid - 128;
        float4 p = red_c[c * 2 + 0];
        float4 q = red_c[c * 2 + 1];
        float mn = fmaxf(p.x, q.x);
        float l = p.y * ex2f(p.x - mn) + q.y * ex2f(q.x - mn);
        g_part[I][col0 + c] = make_float4(mn, l, p.z + q.z, 0.0f);
    }
}

// ---------------- final per-row merge + loss reduction ----------------
__global__ void __launch_bounds__(256)
supcon_reduce(const long long* __restrict__ labels, float* __restrict__ out)
{
    const int wid = threadIdx.x >> 5, lane = threadIdx.x & 31;
    const int row = blockIdx.x * 8 + wid;

    float4 a = g_part[lane][row];
    float4 b = g_part[lane + 32][row];
    float m = fmaxf(a.x, b.x);
    float l = a.y * ex2f(a.x - m) + b.y * ex2f(b.x - m);
    float ps = a.z + b.z;
#pragma unroll
    for (int off = 16; off > 0; off >>= 1) {
        float mo = __shfl_down_sync(0xFFFFFFFFu, m, off);
        float lo = __shfl_down_sync(0xFFFFFFFFu, l, off);
        float po = __shfl_down_sync(0xFFFFFFFFu, ps, off);
        float mn = fmaxf(m, mo);
        l = l * ex2f(m - mn) + lo * ex2f(mo - mn);
        m = mn; ps += po;
    }

    __shared__ float sred[8];
    const float LN2 = 0.6931471805599453f;
    const float T = 0.1f;
    if (lane == 0) {
        float cn = (float)(g_hist[(int)labels[row]] - 1);
        sred[wid] = (m + log2f(l)) * (LN2 * T / (float)NPTS) - ps / (cn * (float)NPTS);
    }
    __syncthreads();
    if (threadIdx.x < 8) {
        float v = sred[threadIdx.x];
#pragma unroll
        for (int off = 4; off > 0; off >>= 1)
            v += __shfl_down_sync(0xFFu, v, off);
        if (threadIdx.x == 0) atomicAdd(out, v);
    }
}

extern "C" void kernel_launch(void* const* d_in, const int* in_sizes, int n_in,
                              void* d_out, int out_size)
{
    const float*     emb    = (const float*)d_in[0];
    const long long* labels = (const long long*)d_in[1];
    float*           out    = (float*)d_out;

    static int configured = 0;
    cudaFuncSetAttribute(supcon_gemm, cudaFuncAttributeMaxDynamicSharedMemorySize, SM_TOTAL);
    (void)configured;

    supcon_zero<<<1, 32>>>(out);
    hist_kernel<<<NPTS / 256, 256>>>(labels);
    conv_kernel<<<NPTS * DDIM / 8 / 256, 256>>>(emb);
    supcon_gemm<<<NTILES_UT, 256, SM_TOTAL>>>(labels);
    supcon_reduce<<<NPTS / 8, 256>>>(labels, out);
}